// round 7
// baseline (speedup 1.0000x reference)
#include <cuda_runtime.h>
#include <cuda_bf16.h>
#include <cstdint>

#define NN 30000
#define NE 300000
#define NB 64

// ---------------- scratch (__device__ globals; allocation-free) ----------------
__device__ float g_x[NN * 64];
__device__ __nv_bfloat16 g_xh[NN * 64], g_xl[NN * 64];
__device__ __nv_bfloat16 g_ehA[NE * 64], g_elA[NE * 64];   // ping
__device__ __nv_bfloat16 g_ehB[NE * 64], g_elB[NE * 64];   // pong
__device__ float g_u[NB * 64];
__device__ __nv_bfloat16 g_uh[NB * 64], g_ul[NB * 64];
__device__ float g_agg[NN * 64];
__device__ float g_pool[NB * 64];
__device__ float g_id[NN], g_cb[NB], g_ib[NB];
__device__ float g_sums[128], g_sc[64], g_sf[64];
__device__ uint32_t g_bfrag[3 * 16384];   // per-layer mma B fragments (hi/lo interleaved)
__device__ int g_hist[NN], g_rowptr[NN + 1], g_cursor[NN], g_elist[NE];

// ---------------- helpers ----------------
__device__ __forceinline__ uint32_t smem_u32(const void* p) {
    uint32_t a;
    asm("{ .reg .u64 t; cvta.to.shared.u64 t, %1; cvt.u32.u64 %0, t; }" : "=r"(a) : "l"(p));
    return a;
}
__device__ __forceinline__ void ldmx4(uint32_t* r, uint32_t addr) {
    asm volatile("ldmatrix.sync.aligned.m8n8.x4.shared.b16 {%0,%1,%2,%3}, [%4];"
                 : "=r"(r[0]), "=r"(r[1]), "=r"(r[2]), "=r"(r[3]) : "r"(addr));
}
__device__ __forceinline__ void lds128(uint32_t* r, uint32_t addr) {
    asm volatile("ld.shared.v4.u32 {%0,%1,%2,%3}, [%4];"
                 : "=r"(r[0]), "=r"(r[1]), "=r"(r[2]), "=r"(r[3]) : "r"(addr));
}
__device__ __forceinline__ void mma16816(float* d, const uint32_t* a, const uint32_t* b) {
    asm volatile(
        "mma.sync.aligned.m16n8k16.row.col.f32.bf16.bf16.f32 "
        "{%0,%1,%2,%3}, {%4,%5,%6,%7}, {%8,%9}, {%0,%1,%2,%3};"
        : "+f"(d[0]), "+f"(d[1]), "+f"(d[2]), "+f"(d[3])
        : "r"(a[0]), "r"(a[1]), "r"(a[2]), "r"(a[3]), "r"(b[0]), "r"(b[1]));
}
__device__ __forceinline__ uint32_t packbf(float a, float b) {
    __nv_bfloat162 t = __floats2bfloat162_rn(a, b);
    return *reinterpret_cast<uint32_t*>(&t);
}

// ---------------- BatchNorm stats: float4 loads + smem reduce ----------------
template <int W>
__global__ void bn_stats4(const float4* __restrict__ in, int n4, float* __restrict__ sums) {
    float s[4] = {0, 0, 0, 0}, s2[4] = {0, 0, 0, 0};
    int stride = gridDim.x * blockDim.x;       // multiple of W/4 (blockDim=256)
    for (int i = blockIdx.x * blockDim.x + threadIdx.x; i < n4; i += stride) {
        float4 v = in[i];
        s[0] += v.x; s2[0] += v.x * v.x;
        s[1] += v.y; s2[1] += v.y * v.y;
        s[2] += v.z; s2[2] += v.z * v.z;
        s[3] += v.w; s2[3] += v.w * v.w;
    }
    __shared__ float sh[2][W];
    if (threadIdx.x < W) { sh[0][threadIdx.x] = 0.f; sh[1][threadIdx.x] = 0.f; }
    __syncthreads();
    int cg = (threadIdx.x & (W / 4 - 1)) * 4;
#pragma unroll
    for (int k = 0; k < 4; k++) {
        atomicAdd(&sh[0][cg + k], s[k]);
        atomicAdd(&sh[1][cg + k], s2[k]);
    }
    __syncthreads();
    if (threadIdx.x < W) {
        atomicAdd(&sums[threadIdx.x], sh[0][threadIdx.x]);
        atomicAdd(&sums[W + threadIdx.x], sh[1][threadIdx.x]);
    }
}

__global__ void bn_finalize(const float* __restrict__ sums, const float* __restrict__ gamma,
                            const float* __restrict__ beta, float inv_rows, int width,
                            float* __restrict__ scale, float* __restrict__ shift) {
    int c = threadIdx.x;
    if (c < width) {
        float mean = sums[c] * inv_rows;
        float var = sums[width + c] * inv_rows - mean * mean;
        float sc = gamma[c] * rsqrtf(var + 1e-5f);
        scale[c] = sc;
        shift[c] = beta[c] - mean * sc;
    }
}

// BN apply + bf16 hi/lo split variants
__global__ void bn_split_x(const float* __restrict__ in, const float* __restrict__ sc,
                           const float* __restrict__ sf, float* __restrict__ xf,
                           __nv_bfloat16* __restrict__ xh, __nv_bfloat16* __restrict__ xl) {
    int i = blockIdx.x * blockDim.x + threadIdx.x;
    if (i < NN * 64) {
        int c = i & 63;
        float v = fmaf(in[i], sc[c], sf[c]);
        xf[i] = v;
        __nv_bfloat16 h = __float2bfloat16(v);
        xh[i] = h;
        xl[i] = __float2bfloat16(v - __bfloat162float(h));
    }
}
__global__ void bn_split_e(const float* __restrict__ in, const float* __restrict__ sc,
                           const float* __restrict__ sf,
                           __nv_bfloat16* __restrict__ eh, __nv_bfloat16* __restrict__ el) {
    int i = blockIdx.x * blockDim.x + threadIdx.x;
    if (i < NE * 32) {
        int c = i & 31;
        float v = fmaf(in[i], sc[c], sf[c]);
        __nv_bfloat16 h = __float2bfloat16(v);
        eh[i] = h;
        el[i] = __float2bfloat16(v - __bfloat162float(h));
    }
}
__global__ void bn_split_u(const float* __restrict__ in, const float* __restrict__ sc,
                           const float* __restrict__ sf, float* __restrict__ uf,
                           __nv_bfloat16* __restrict__ uh, __nv_bfloat16* __restrict__ ul) {
    int i = blockIdx.x * blockDim.x + threadIdx.x;
    if (i < NB * 32) {
        int b = i >> 5, c = i & 31;
        float v = fmaf(in[i], sc[c], sf[c]);
        uf[b * 64 + c] = v;
        __nv_bfloat16 h = __float2bfloat16(v);
        uh[b * 64 + c] = h;
        ul[b * 64 + c] = __float2bfloat16(v - __bfloat162float(h));
    }
}

// ---- pack W [K x 64] into mma.m16n8k16 B-fragment order, hi/lo ----
__global__ void bfrag_pack(const float* __restrict__ W, int K, uint32_t* __restrict__ out) {
    int i = blockIdx.x * blockDim.x + threadIdx.x;
    int total = (K / 16) * 8 * 32;
    if (i >= total) return;
    int lane = i & 31;
    int nt = (i >> 5) & 7;
    int kt = i >> 8;
    int n = nt * 8 + (lane >> 2);
    int k0 = kt * 16 + 2 * (lane & 3);
    float v00 = W[k0 * 64 + n],       v01 = W[(k0 + 1) * 64 + n];
    float v10 = W[(k0 + 8) * 64 + n], v11 = W[(k0 + 9) * 64 + n];
    float h00 = __bfloat162float(__float2bfloat16(v00));
    float h01 = __bfloat162float(__float2bfloat16(v01));
    float h10 = __bfloat162float(__float2bfloat16(v10));
    float h11 = __bfloat162float(__float2bfloat16(v11));
    out[4 * i + 0] = packbf(v00, v01);
    out[4 * i + 1] = packbf(v10, v11);
    out[4 * i + 2] = packbf(v00 - h00, v01 - h01);
    out[4 * i + 3] = packbf(v10 - h10, v11 - h11);
}

// ---------------- CSR build: hist -> scan -> scatter ----------------
__global__ void hist_dst(const int* __restrict__ dst, int* __restrict__ cnt) {
    int i = blockIdx.x * blockDim.x + threadIdx.x;
    if (i < NE) atomicAdd(&cnt[dst[i]], 1);
}
__global__ void csr_scan(const int* __restrict__ cnt, int* __restrict__ rowptr,
                         int* __restrict__ cursor, float* __restrict__ inv) {
    __shared__ int ps[1024];
    int t = threadIdx.x;
    const int CH = (NN + 1023) / 1024;   // 30
    int base = t * CH;
    int s = 0;
#pragma unroll
    for (int i = 0; i < CH; i++) { int id = base + i; if (id < NN) s += cnt[id]; }
    ps[t] = s;
    __syncthreads();
    for (int d = 1; d < 1024; d <<= 1) {
        int v = (t >= d) ? ps[t - d] : 0;
        __syncthreads();
        ps[t] += v;
        __syncthreads();
    }
    int off = (t == 0) ? 0 : ps[t - 1];
    for (int i = 0; i < CH; i++) {
        int id = base + i;
        if (id < NN) {
            rowptr[id] = off;
            cursor[id] = off;
            int c = cnt[id];
            inv[id] = 1.f / (float)max(c, 1);
            off += c;
        }
    }
    if (t == 1023) rowptr[NN] = NE;
}
__global__ void csr_scatter(const int* __restrict__ dst, int* __restrict__ cursor,
                            int* __restrict__ elist) {
    int i = blockIdx.x * blockDim.x + threadIdx.x;
    if (i < NE) {
        int p = atomicAdd(&cursor[dst[i]], 1);
        elist[p] = i;
    }
}

// ---------------- aggregation: CSR gather (no atomics) ----------------
// warp per node; lane sums cols (2*lane, 2*lane+1) over incoming edges.
__global__ void agg_gather_bf(const uint32_t* __restrict__ eh, const uint32_t* __restrict__ el,
                              const int* __restrict__ rowptr, const int* __restrict__ elist,
                              float* __restrict__ agg) {
    int warp = (blockIdx.x * blockDim.x + threadIdx.x) >> 5;
    int lane = threadIdx.x & 31;
    if (warp >= NN) return;
    int beg = rowptr[warp], end = rowptr[warp + 1];
    float a0 = 0.f, a1 = 0.f;
    for (int j = beg; j < end; j++) {
        int eid = elist[j];
        uint32_t h = eh[eid * 32 + lane];
        uint32_t l = el[eid * 32 + lane];
        __nv_bfloat162 hh = *reinterpret_cast<__nv_bfloat162*>(&h);
        __nv_bfloat162 ll = *reinterpret_cast<__nv_bfloat162*>(&l);
        a0 += __low2float(hh) + __low2float(ll);
        a1 += __high2float(hh) + __high2float(ll);
    }
    reinterpret_cast<float2*>(agg)[warp * 32 + lane] = make_float2(a0, a1);
}
__global__ void agg_gather_f32(const float2* __restrict__ e, const int* __restrict__ rowptr,
                               const int* __restrict__ elist, float* __restrict__ agg) {
    int warp = (blockIdx.x * blockDim.x + threadIdx.x) >> 5;
    int lane = threadIdx.x & 31;
    if (warp >= NN) return;
    int beg = rowptr[warp], end = rowptr[warp + 1];
    float a0 = 0.f, a1 = 0.f;
    for (int j = beg; j < end; j++) {
        float2 v = e[elist[j] * 32 + lane];
        a0 += v.x; a1 += v.y;
    }
    reinterpret_cast<float2*>(agg)[warp * 32 + lane] = make_float2(a0, a1);
}

// ---------------- batch counts ----------------
__global__ void count_idx(const int* __restrict__ idx, float* __restrict__ cnt, int n) {
    int i = blockIdx.x * blockDim.x + threadIdx.x;
    if (i < n) atomicAdd(&cnt[idx[i]], 1.f);
}
__global__ void make_inv(const float* __restrict__ cnt, float* __restrict__ inv, int n) {
    int i = blockIdx.x * blockDim.x + threadIdx.x;
    if (i < n) inv[i] = 1.f / fmaxf(cnt[i], 1.f);
}

// ---------------- edge MLP via mma.sync bf16-split GEMM ----------------
template <int K, int EW, bool FINAL>
__global__ void __launch_bounds__(256, 1)
edge_gemm(const __nv_bfloat16* __restrict__ xh, const __nv_bfloat16* __restrict__ xl,
          const __nv_bfloat16* __restrict__ ehi, const __nv_bfloat16* __restrict__ eli,
          const __nv_bfloat16* __restrict__ uh, const __nv_bfloat16* __restrict__ ul,
          const int* __restrict__ src, const int* __restrict__ dst,
          const int* __restrict__ batch,
          const uint32_t* __restrict__ bfrag, const float* __restrict__ bias,
          float* __restrict__ e_out, __nv_bfloat16* __restrict__ eho,
          __nv_bfloat16* __restrict__ elo) {
    constexpr int RU = K / 8;            // 16B chunks per row
    constexpr int NKT = K / 16;          // k-tiles
    constexpr int LDA = K * 2 + 16;      // padded row pitch (bytes)
    constexpr int ASZ = 128 * LDA;
    constexpr int SM_A = 2048;
    constexpr int SM_B = SM_A + 2 * ASZ;
    constexpr int BF_U32 = NKT * 8 * 32 * 4;

    extern __shared__ char smem[];
    float* biasS = (float*)smem;
    int* sT = (int*)(smem + 256);
    int* dT = (int*)(smem + 768);
    int* bT = (int*)(smem + 1280);
    const uint32_t sb = smem_u32(smem);

    const int tid = threadIdx.x;
    const int wid = tid >> 5;
    const int lane = tid & 31;
    const int ebase = blockIdx.x * 128;

    if (tid < 128) {
        int ee = min(ebase + tid, NE - 1);
        int s = src[ee];
        sT[tid] = s; dT[tid] = dst[ee]; bT[tid] = batch[s];
    }
    if (tid < 64) biasS[tid] = bias[tid];
    __syncthreads();

    // ---- stage A (gathered rows, hi at SM_A, lo at SM_A+ASZ) ----
    for (int it = tid; it < 128 * RU; it += 256) {
        int r = it / RU, j = it - r * RU;
        const uint4 *ph, *pl;
        if (j < 8) {
            int o = sT[r] * 8 + j;
            ph = (const uint4*)xh + o; pl = (const uint4*)xl + o;
        } else if (j < 16) {
            int o = dT[r] * 8 + (j - 8);
            ph = (const uint4*)xh + o; pl = (const uint4*)xl + o;
        } else if (j < 16 + EW / 8) {
            int ee = min(ebase + r, NE - 1);
            int o = ee * (EW / 8) + (j - 16);
            ph = (const uint4*)ehi + o; pl = (const uint4*)eli + o;
        } else {
            int o = bT[r] * 8 + (j - 16 - EW / 8);
            ph = (const uint4*)uh + o; pl = (const uint4*)ul + o;
        }
        uint32_t da = sb + SM_A + r * LDA + j * 16;
        uint4 vh = *ph, vl = *pl;
        asm volatile("st.shared.v4.b32 [%0], {%1, %2, %3, %4};" :: "r"(da),
                     "r"(vh.x), "r"(vh.y), "r"(vh.z), "r"(vh.w) : "memory");
        asm volatile("st.shared.v4.b32 [%0], {%1, %2, %3, %4};" :: "r"(da + ASZ),
                     "r"(vl.x), "r"(vl.y), "r"(vl.z), "r"(vl.w) : "memory");
    }
    // ---- stage B fragments ----
    {
        const uint4* s4 = (const uint4*)bfrag;
        uint4* d4 = (uint4*)(smem + SM_B);
        for (int i = tid; i < BF_U32 / 4; i += 256) d4[i] = s4[i];
    }
    __syncthreads();

    // ---- mma mainloop ----
    float acc[8][4];
#pragma unroll
    for (int nt = 0; nt < 8; nt++)
#pragma unroll
        for (int r = 0; r < 4; r++) acc[nt][r] = 0.f;

    const uint32_t arow = sb + SM_A + (wid * 16 + (lane & 15)) * LDA + (lane >> 4) * 16;
#pragma unroll
    for (int kt = 0; kt < NKT; kt++) {
        uint32_t Ah[4], Al[4];
        ldmx4(Ah, arow + kt * 32);
        ldmx4(Al, arow + kt * 32 + ASZ);
        const uint32_t baddr = sb + SM_B + (uint32_t)(kt * 8 * 32 + lane) * 16;
#pragma unroll
        for (int nt = 0; nt < 8; nt++) {
            uint32_t bb[4];
            lds128(bb, baddr + nt * 512);
            mma16816(acc[nt], Ah, bb);       // hi * hi
            mma16816(acc[nt], Al, bb);       // lo * hi
            mma16816(acc[nt], Ah, bb + 2);   // hi * lo
        }
    }

    // ---- epilogue (no atomics; aggregation handled by CSR gather) ----
    const int r0 = wid * 16 + (lane >> 2);
    const int cbase = 2 * (lane & 3);
#pragma unroll
    for (int half = 0; half < 2; half++) {
        int row = r0 + 8 * half;
        int ee = ebase + row;
        if (ee < NE) {
            if (FINAL) {
                float* eo = e_out + (size_t)ee * 64 + cbase;
#pragma unroll
                for (int nt = 0; nt < 8; nt++) {
                    int c0 = nt * 8 + cbase;
                    float v0 = fmaxf(acc[nt][2 * half] + biasS[c0], 0.f);
                    float v1 = fmaxf(acc[nt][2 * half + 1] + biasS[c0 + 1], 0.f);
                    asm volatile("st.global.v2.f32 [%0], {%1,%2};"
                                 :: "l"(eo + nt * 8), "f"(v0), "f"(v1) : "memory");
                }
            } else {
                uint32_t* ho = (uint32_t*)eho + (size_t)ee * 32 + (lane & 3);
                uint32_t* lo = (uint32_t*)elo + (size_t)ee * 32 + (lane & 3);
#pragma unroll
                for (int nt = 0; nt < 8; nt++) {
                    int c0 = nt * 8 + cbase;
                    float v0 = fmaxf(acc[nt][2 * half] + biasS[c0], 0.f);
                    float v1 = fmaxf(acc[nt][2 * half + 1] + biasS[c0 + 1], 0.f);
                    float h0 = __bfloat162float(__float2bfloat16(v0));
                    float h1 = __bfloat162float(__float2bfloat16(v1));
                    ho[nt * 4] = packbf(v0, v1);
                    lo[nt * 4] = packbf(v0 - h0, v1 - h1);
                }
            }
        }
    }
}

// ---------------- node MLP (warp-shuffle fp32) + fused pool + fused split ----------------
template <int DIN, int UW, bool FINAL>
__global__ void node_mlp(const float* __restrict__ x_in, const float* __restrict__ agg,
                         const float* __restrict__ inv_dst, const float* __restrict__ u,
                         const int* __restrict__ batch, const float* __restrict__ W,
                         const float* __restrict__ bias, float* __restrict__ x_out,
                         float* __restrict__ pool,
                         __nv_bfloat16* __restrict__ xh, __nv_bfloat16* __restrict__ xl) {
    extern __shared__ float Wsh[];
    for (int i = threadIdx.x; i < DIN * 64; i += blockDim.x) Wsh[i] = W[i];
    __syncthreads();
    const int lane = threadIdx.x & 31;
    const int warp = threadIdx.x >> 5;
    const int nwarp = blockDim.x >> 5;
    const float b0 = bias[lane], b1 = bias[lane + 32];
    constexpr int EPW = 4;
    constexpr int NCH = DIN / 32;

    for (int nbase = (blockIdx.x * nwarp + warp) * EPW; nbase < NN;
         nbase += gridDim.x * nwarp * EPW) {
        int ns[EPW], bN[EPW];
        float rc[EPW], acc0[EPW], acc1[EPW];
#pragma unroll
        for (int i = 0; i < EPW; i++) {
            int nn = min(nbase + i, NN - 1);
            ns[i] = nn; bN[i] = batch[nn]; rc[i] = inv_dst[nn];
            acc0[i] = b0; acc1[i] = b1;
        }
#pragma unroll
        for (int c = 0; c < NCH; c++) {
            float v[EPW];
#pragma unroll
            for (int i = 0; i < EPW; i++) {
                if (c < 2)       v[i] = x_in[ns[i] * 64 + c * 32 + lane];
                else if (c < 4)  v[i] = agg[ns[i] * 64 + (c - 2) * 32 + lane] * rc[i];
                else             v[i] = u[bN[i] * 64 + (c - 4) * 32 + lane];
            }
#pragma unroll
            for (int t = 0; t < 32; t++) {
                float w0 = Wsh[(c * 32 + t) * 64 + lane];
                float w1 = Wsh[(c * 32 + t) * 64 + 32 + lane];
#pragma unroll
                for (int i = 0; i < EPW; i++) {
                    float s = __shfl_sync(0xffffffffu, v[i], t);
                    acc0[i] = fmaf(s, w0, acc0[i]);
                    acc1[i] = fmaf(s, w1, acc1[i]);
                }
            }
        }
#pragma unroll
        for (int i = 0; i < EPW; i++) {
            if (nbase + i < NN) {
                float v0 = fmaxf(acc0[i], 0.f), v1 = fmaxf(acc1[i], 0.f);
                x_out[ns[i] * 64 + lane] = v0;
                x_out[ns[i] * 64 + 32 + lane] = v1;
                atomicAdd(&pool[bN[i] * 64 + lane], v0);
                atomicAdd(&pool[bN[i] * 64 + 32 + lane], v1);
                if (!FINAL) {
                    __nv_bfloat16 h0 = __float2bfloat16(v0);
                    __nv_bfloat16 h1 = __float2bfloat16(v1);
                    xh[ns[i] * 64 + lane] = h0;
                    xh[ns[i] * 64 + 32 + lane] = h1;
                    xl[ns[i] * 64 + lane] = __float2bfloat16(v0 - __bfloat162float(h0));
                    xl[ns[i] * 64 + 32 + lane] = __float2bfloat16(v1 - __bfloat162float(h1));
                }
            }
        }
    }
}

// ---------------- global MLP + fused split ----------------
template <int UW, bool FINAL>
__global__ void glob_mlp(const float* __restrict__ xpool, const float* __restrict__ invb,
                         const float* __restrict__ u_in, const float* __restrict__ W,
                         const float* __restrict__ bias, float* __restrict__ u_out,
                         __nv_bfloat16* __restrict__ uh, __nv_bfloat16* __restrict__ ul) {
    __shared__ float us[64];
    __shared__ float ps[64];
    int b = blockIdx.x;
    int h = threadIdx.x;
    if (h < UW) us[h] = u_in[b * 64 + h];
    ps[h] = xpool[b * 64 + h] * invb[b];
    __syncthreads();
    float acc = bias[h];
#pragma unroll 8
    for (int d = 0; d < 64; d++) acc = fmaf(ps[d], W[d * 64 + h], acc);
#pragma unroll 8
    for (int d = 0; d < UW; d++) acc = fmaf(us[d], W[(64 + d) * 64 + h], acc);
    float v = fmaxf(acc, 0.f);
    u_out[b * 64 + h] = v;
    if (!FINAL) {
        __nv_bfloat16 hb = __float2bfloat16(v);
        uh[b * 64 + h] = hb;
        ul[b * 64 + h] = __float2bfloat16(v - __bfloat162float(hb));
    }
}

// ---------------- host orchestration ----------------
extern "C" void kernel_launch(void* const* d_in, const int* in_sizes, int n_in,
                              void* d_out, int out_size) {
    const float* x     = (const float*)d_in[0];
    const int*   eidx  = (const int*)d_in[1];
    const float* e     = (const float*)d_in[2];
    const float* u     = (const float*)d_in[3];
    const int*   batch = (const int*)d_in[4];
    const float* gn = (const float*)d_in[5],  *bnb = (const float*)d_in[6];
    const float* ge = (const float*)d_in[7],  *beb = (const float*)d_in[8];
    const float* gg = (const float*)d_in[9],  *bgb = (const float*)d_in[10];
    const float* We[3] = {(const float*)d_in[11], (const float*)d_in[17], (const float*)d_in[23]};
    const float* be[3] = {(const float*)d_in[12], (const float*)d_in[18], (const float*)d_in[24]};
    const float* Wn[3] = {(const float*)d_in[13], (const float*)d_in[19], (const float*)d_in[25]};
    const float* bn[3] = {(const float*)d_in[14], (const float*)d_in[20], (const float*)d_in[26]};
    const float* Wg[3] = {(const float*)d_in[15], (const float*)d_in[21], (const float*)d_in[27]};
    const float* bg[3] = {(const float*)d_in[16], (const float*)d_in[22], (const float*)d_in[28]};

    const int* src = eidx;
    const int* dst = eidx + NE;

    float* out_x = (float*)d_out;
    float* out_e = out_x + (size_t)NN * 64;
    float* out_u = out_e + (size_t)NE * 64;

    float *p_x, *p_u, *p_agg, *p_pool, *p_cb, *p_id, *p_ib, *p_sums, *p_sc, *p_sf;
    __nv_bfloat16 *p_xh, *p_xl, *p_ehA, *p_elA, *p_ehB, *p_elB, *p_uh, *p_ul;
    uint32_t* p_bf;
    int *p_hist, *p_rowptr, *p_cursor, *p_elist;
    cudaGetSymbolAddress((void**)&p_x, g_x);
    cudaGetSymbolAddress((void**)&p_u, g_u);
    cudaGetSymbolAddress((void**)&p_agg, g_agg);
    cudaGetSymbolAddress((void**)&p_pool, g_pool);
    cudaGetSymbolAddress((void**)&p_cb, g_cb);
    cudaGetSymbolAddress((void**)&p_id, g_id);
    cudaGetSymbolAddress((void**)&p_ib, g_ib);
    cudaGetSymbolAddress((void**)&p_sums, g_sums);
    cudaGetSymbolAddress((void**)&p_sc, g_sc);
    cudaGetSymbolAddress((void**)&p_sf, g_sf);
    cudaGetSymbolAddress((void**)&p_xh, g_xh);
    cudaGetSymbolAddress((void**)&p_xl, g_xl);
    cudaGetSymbolAddress((void**)&p_ehA, g_ehA);
    cudaGetSymbolAddress((void**)&p_elA, g_elA);
    cudaGetSymbolAddress((void**)&p_ehB, g_ehB);
    cudaGetSymbolAddress((void**)&p_elB, g_elB);
    cudaGetSymbolAddress((void**)&p_uh, g_uh);
    cudaGetSymbolAddress((void**)&p_ul, g_ul);
    cudaGetSymbolAddress((void**)&p_bf, g_bfrag);
    cudaGetSymbolAddress((void**)&p_hist, g_hist);
    cudaGetSymbolAddress((void**)&p_rowptr, g_rowptr);
    cudaGetSymbolAddress((void**)&p_cursor, g_cursor);
    cudaGetSymbolAddress((void**)&p_elist, g_elist);

    const int SM192 = 2048 + 2 * (128 * (192 * 2 + 16)) + (192 / 16) * 8 * 32 * 16;
    const int SM256 = 2048 + 2 * (128 * (256 * 2 + 16)) + (256 / 16) * 8 * 32 * 16;
    cudaFuncSetAttribute(edge_gemm<192, 32, false>, cudaFuncAttributeMaxDynamicSharedMemorySize, SM192);
    cudaFuncSetAttribute(edge_gemm<256, 64, false>, cudaFuncAttributeMaxDynamicSharedMemorySize, SM256);
    cudaFuncSetAttribute(edge_gemm<256, 64, true>,  cudaFuncAttributeMaxDynamicSharedMemorySize, SM256);
    cudaFuncSetAttribute(node_mlp<160, 32, false>, cudaFuncAttributeMaxDynamicSharedMemorySize, 160 * 64 * 4);
    cudaFuncSetAttribute(node_mlp<192, 64, false>, cudaFuncAttributeMaxDynamicSharedMemorySize, 192 * 64 * 4);
    cudaFuncSetAttribute(node_mlp<192, 64, true>,  cudaFuncAttributeMaxDynamicSharedMemorySize, 192 * 64 * 4);

    // ---- CSR build (overlaps with BN work) ----
    cudaMemsetAsync(p_hist, 0, NN * sizeof(int));
    hist_dst<<<(NE + 255) / 256, 256>>>(dst, p_hist);
    csr_scan<<<1, 1024>>>(p_hist, p_rowptr, p_cursor, p_id);
    csr_scatter<<<(NE + 255) / 256, 256>>>(dst, p_cursor, p_elist);

    // ---- input BatchNorms + splits ----
    cudaMemsetAsync(p_sums, 0, 128 * sizeof(float));
    bn_stats4<64><<<296, 256>>>((const float4*)x, NN * 16, p_sums);
    bn_finalize<<<1, 64>>>(p_sums, gn, bnb, 1.f / NN, 64, p_sc, p_sf);
    bn_split_x<<<(NN * 64 + 255) / 256, 256>>>(x, p_sc, p_sf, p_x, p_xh, p_xl);

    cudaMemsetAsync(p_sums, 0, 128 * sizeof(float));
    bn_stats4<32><<<592, 256>>>((const float4*)e, NE * 8, p_sums);
    bn_finalize<<<1, 64>>>(p_sums, ge, beb, 1.f / NE, 32, p_sc, p_sf);
    bn_split_e<<<(NE * 32 + 255) / 256, 256>>>(e, p_sc, p_sf, p_ehA, p_elA);

    cudaMemsetAsync(p_sums, 0, 128 * sizeof(float));
    bn_stats4<32><<<2, 256>>>((const float4*)u, NB * 8, p_sums);
    bn_finalize<<<1, 64>>>(p_sums, gg, bgb, 1.f / NB, 32, p_sc, p_sf);
    bn_split_u<<<(NB * 32 + 63) / 64, 64>>>(u, p_sc, p_sf, p_u, p_uh, p_ul);

    // ---- batch counts ----
    cudaMemsetAsync(p_cb, 0, NB * sizeof(float));
    count_idx<<<(NN + 255) / 256, 256>>>(batch, p_cb, NN);
    make_inv<<<1, 64>>>(p_cb, p_ib, NB);

    // ---- pack edge weights into mma B-fragment order (hi/lo) ----
    bfrag_pack<<<(12 * 256 + 255) / 256, 256>>>(We[0], 192, p_bf + 0 * 16384);
    bfrag_pack<<<(16 * 256 + 255) / 256, 256>>>(We[1], 256, p_bf + 1 * 16384);
    bfrag_pack<<<(16 * 256 + 255) / 256, 256>>>(We[2], 256, p_bf + 2 * 16384);

    const int EGRID = (NE + 127) / 128;
    const int NGRID = 938;
    const int AGRID = (NN * 32 + 255) / 256;   // warp per node, 8 warps/block

    // ---- layer 0 ----
    edge_gemm<192, 32, false><<<EGRID, 256, SM192>>>(
        p_xh, p_xl, p_ehA, p_elA, p_uh, p_ul, src, dst, batch,
        p_bf + 0 * 16384, be[0], nullptr, p_ehB, p_elB);
    agg_gather_bf<<<AGRID, 256>>>((const uint32_t*)p_ehB, (const uint32_t*)p_elB,
                                  p_rowptr, p_elist, p_agg);
    cudaMemsetAsync(p_pool, 0, NB * 64 * sizeof(float));
    node_mlp<160, 32, false><<<NGRID, 256, 160 * 64 * 4>>>(
        p_x, p_agg, p_id, p_u, batch, Wn[0], bn[0], p_x, p_pool, p_xh, p_xl);
    glob_mlp<32, false><<<NB, 64>>>(p_pool, p_ib, p_u, Wg[0], bg[0], p_u, p_uh, p_ul);

    // ---- layer 1 ----
    edge_gemm<256, 64, false><<<EGRID, 256, SM256>>>(
        p_xh, p_xl, p_ehB, p_elB, p_uh, p_ul, src, dst, batch,
        p_bf + 1 * 16384, be[1], nullptr, p_ehA, p_elA);
    agg_gather_bf<<<AGRID, 256>>>((const uint32_t*)p_ehA, (const uint32_t*)p_elA,
                                  p_rowptr, p_elist, p_agg);
    cudaMemsetAsync(p_pool, 0, NB * 64 * sizeof(float));
    node_mlp<192, 64, false><<<NGRID, 256, 192 * 64 * 4>>>(
        p_x, p_agg, p_id, p_u, batch, Wn[1], bn[1], p_x, p_pool, p_xh, p_xl);
    glob_mlp<64, false><<<NB, 64>>>(p_pool, p_ib, p_u, Wg[1], bg[1], p_u, p_uh, p_ul);

    // ---- layer 2 (final: write out_e / out_x / out_u) ----
    edge_gemm<256, 64, true><<<EGRID, 256, SM256>>>(
        p_xh, p_xl, p_ehA, p_elA, p_uh, p_ul, src, dst, batch,
        p_bf + 2 * 16384, be[2], out_e, nullptr, nullptr);
    agg_gather_f32<<<AGRID, 256>>>((const float2*)out_e, p_rowptr, p_elist, p_agg);
    cudaMemsetAsync(p_pool, 0, NB * 64 * sizeof(float));
    node_mlp<192, 64, true><<<NGRID, 256, 192 * 64 * 4>>>(
        p_x, p_agg, p_id, p_u, batch, Wn[2], bn[2], out_x, p_pool, nullptr, nullptr);
    glob_mlp<64, true><<<NB, 64>>>(p_pool, p_ib, p_u, Wg[2], bg[2], out_u, nullptr, nullptr);
}

// round 8
// speedup vs baseline: 1.8523x; 1.8523x over previous
#include <cuda_runtime.h>
#include <cuda_bf16.h>
#include <cstdint>

#define NN 30000
#define NE 300000
#define NB 64

// ---------------- scratch (__device__ globals; allocation-free) ----------------
__device__ float g_x[NN * 64];
__device__ __nv_bfloat16 g_xh[NN * 64], g_xl[NN * 64];
__device__ __nv_bfloat16 g_ehA[NE * 64], g_elA[NE * 64];   // ping
__device__ __nv_bfloat16 g_ehB[NE * 64], g_elB[NE * 64];   // pong
__device__ float g_u[NB * 64];
__device__ float g_P[NN * 128];          // P = x @ [We1|We2]
__device__ float g_PU[NB * 64];          // PU = u @ We4 + be
__device__ float g_agg[NN * 64];
__device__ float g_pool[NB * 64];
__device__ float g_id[NN], g_cb[NB], g_ib[NB];
__device__ float g_sums[128], g_sc[64], g_sf[64];
__device__ uint32_t g_bfe[3 * 4096];     // edge We3 fragments (K<=64, N=64)
__device__ uint32_t g_bfp[3 * 8192];     // P [We1|We2] fragments (K=64, N=128)
__device__ int g_hist[NN], g_rowptr[NN + 1], g_cursor[NN], g_elist[NE];

// ---------------- helpers ----------------
__device__ __forceinline__ uint32_t smem_u32(const void* p) {
    uint32_t a;
    asm("{ .reg .u64 t; cvta.to.shared.u64 t, %1; cvt.u32.u64 %0, t; }" : "=r"(a) : "l"(p));
    return a;
}
__device__ __forceinline__ void ldmx4(uint32_t* r, uint32_t addr) {
    asm volatile("ldmatrix.sync.aligned.m8n8.x4.shared.b16 {%0,%1,%2,%3}, [%4];"
                 : "=r"(r[0]), "=r"(r[1]), "=r"(r[2]), "=r"(r[3]) : "r"(addr));
}
__device__ __forceinline__ void lds128(uint32_t* r, uint32_t addr) {
    asm volatile("ld.shared.v4.u32 {%0,%1,%2,%3}, [%4];"
                 : "=r"(r[0]), "=r"(r[1]), "=r"(r[2]), "=r"(r[3]) : "r"(addr));
}
__device__ __forceinline__ void mma16816(float* d, const uint32_t* a, const uint32_t* b) {
    asm volatile(
        "mma.sync.aligned.m16n8k16.row.col.f32.bf16.bf16.f32 "
        "{%0,%1,%2,%3}, {%4,%5,%6,%7}, {%8,%9}, {%0,%1,%2,%3};"
        : "+f"(d[0]), "+f"(d[1]), "+f"(d[2]), "+f"(d[3])
        : "r"(a[0]), "r"(a[1]), "r"(a[2]), "r"(a[3]), "r"(b[0]), "r"(b[1]));
}
__device__ __forceinline__ uint32_t packbf(float a, float b) {
    __nv_bfloat162 t = __floats2bfloat162_rn(a, b);
    return *reinterpret_cast<uint32_t*>(&t);
}

// ---------------- BatchNorm stats: float4 loads + smem reduce ----------------
template <int W>
__global__ void bn_stats4(const float4* __restrict__ in, int n4, float* __restrict__ sums) {
    float s[4] = {0, 0, 0, 0}, s2[4] = {0, 0, 0, 0};
    int stride = gridDim.x * blockDim.x;
    for (int i = blockIdx.x * blockDim.x + threadIdx.x; i < n4; i += stride) {
        float4 v = in[i];
        s[0] += v.x; s2[0] += v.x * v.x;
        s[1] += v.y; s2[1] += v.y * v.y;
        s[2] += v.z; s2[2] += v.z * v.z;
        s[3] += v.w; s2[3] += v.w * v.w;
    }
    __shared__ float sh[2][W];
    if (threadIdx.x < W) { sh[0][threadIdx.x] = 0.f; sh[1][threadIdx.x] = 0.f; }
    __syncthreads();
    int cg = (threadIdx.x & (W / 4 - 1)) * 4;
#pragma unroll
    for (int k = 0; k < 4; k++) {
        atomicAdd(&sh[0][cg + k], s[k]);
        atomicAdd(&sh[1][cg + k], s2[k]);
    }
    __syncthreads();
    if (threadIdx.x < W) {
        atomicAdd(&sums[threadIdx.x], sh[0][threadIdx.x]);
        atomicAdd(&sums[W + threadIdx.x], sh[1][threadIdx.x]);
    }
}

__global__ void bn_finalize(const float* __restrict__ sums, const float* __restrict__ gamma,
                            const float* __restrict__ beta, float inv_rows, int width,
                            float* __restrict__ scale, float* __restrict__ shift) {
    int c = threadIdx.x;
    if (c < width) {
        float mean = sums[c] * inv_rows;
        float var = sums[width + c] * inv_rows - mean * mean;
        float sc = gamma[c] * rsqrtf(var + 1e-5f);
        scale[c] = sc;
        shift[c] = beta[c] - mean * sc;
    }
}

__global__ void bn_split_x(const float* __restrict__ in, const float* __restrict__ sc,
                           const float* __restrict__ sf, float* __restrict__ xf,
                           __nv_bfloat16* __restrict__ xh, __nv_bfloat16* __restrict__ xl) {
    int i = blockIdx.x * blockDim.x + threadIdx.x;
    if (i < NN * 64) {
        int c = i & 63;
        float v = fmaf(in[i], sc[c], sf[c]);
        xf[i] = v;
        __nv_bfloat16 h = __float2bfloat16(v);
        xh[i] = h;
        xl[i] = __float2bfloat16(v - __bfloat162float(h));
    }
}
__global__ void bn_split_e(const float* __restrict__ in, const float* __restrict__ sc,
                           const float* __restrict__ sf,
                           __nv_bfloat16* __restrict__ eh, __nv_bfloat16* __restrict__ el) {
    int i = blockIdx.x * blockDim.x + threadIdx.x;
    if (i < NE * 32) {
        int c = i & 31;
        float v = fmaf(in[i], sc[c], sf[c]);
        __nv_bfloat16 h = __float2bfloat16(v);
        eh[i] = h;
        el[i] = __float2bfloat16(v - __bfloat162float(h));
    }
}
__global__ void bn_apply_u(const float* __restrict__ in, const float* __restrict__ sc,
                           const float* __restrict__ sf, float* __restrict__ uf) {
    int i = blockIdx.x * blockDim.x + threadIdx.x;
    if (i < NB * 32) {
        int b = i >> 5, c = i & 31;
        uf[b * 64 + c] = fmaf(in[i], sc[c], sf[c]);
    }
}

// ---- pack W[koff + k][n] (64-wide rows) into mma B-frag order (N=64), hi/lo ----
__global__ void bfrag_pack(const float* __restrict__ W, int K, uint32_t* __restrict__ out) {
    int i = blockIdx.x * blockDim.x + threadIdx.x;
    int total = (K / 16) * 8 * 32;
    if (i >= total) return;
    int lane = i & 31;
    int nt = (i >> 5) & 7;
    int kt = i >> 8;
    int n = nt * 8 + (lane >> 2);
    int k0 = kt * 16 + 2 * (lane & 3);
    float v00 = W[k0 * 64 + n],       v01 = W[(k0 + 1) * 64 + n];
    float v10 = W[(k0 + 8) * 64 + n], v11 = W[(k0 + 9) * 64 + n];
    float h00 = __bfloat162float(__float2bfloat16(v00));
    float h01 = __bfloat162float(__float2bfloat16(v01));
    float h10 = __bfloat162float(__float2bfloat16(v10));
    float h11 = __bfloat162float(__float2bfloat16(v11));
    out[4 * i + 0] = packbf(v00, v01);
    out[4 * i + 1] = packbf(v10, v11);
    out[4 * i + 2] = packbf(v00 - h00, v01 - h01);
    out[4 * i + 3] = packbf(v10 - h10, v11 - h11);
}

// ---- pack combined [We1|We2] (N=128, K=64): n<64 -> W[k][n]; n>=64 -> W[64+k][n-64] ----
__global__ void bfrag_pack_p(const float* __restrict__ W, uint32_t* __restrict__ out) {
    int i = blockIdx.x * blockDim.x + threadIdx.x;
    const int total = 4 * 16 * 32;    // kt * nt * lane
    if (i >= total) return;
    int lane = i & 31;
    int nt = (i >> 5) & 15;
    int kt = i >> 9;
    int n = nt * 8 + (lane >> 2);
    int k0 = kt * 16 + 2 * (lane & 3);
    int roff = (n < 64) ? 0 : 64;
    int col = n & 63;
    float v00 = W[(roff + k0) * 64 + col],     v01 = W[(roff + k0 + 1) * 64 + col];
    float v10 = W[(roff + k0 + 8) * 64 + col], v11 = W[(roff + k0 + 9) * 64 + col];
    float h00 = __bfloat162float(__float2bfloat16(v00));
    float h01 = __bfloat162float(__float2bfloat16(v01));
    float h10 = __bfloat162float(__float2bfloat16(v10));
    float h11 = __bfloat162float(__float2bfloat16(v11));
    out[4 * i + 0] = packbf(v00, v01);
    out[4 * i + 1] = packbf(v10, v11);
    out[4 * i + 2] = packbf(v00 - h00, v01 - h01);
    out[4 * i + 3] = packbf(v10 - h10, v11 - h11);
}

// ---------------- CSR build: hist -> scan -> scatter ----------------
__global__ void hist_dst(const int* __restrict__ dst, int* __restrict__ cnt) {
    int i = blockIdx.x * blockDim.x + threadIdx.x;
    if (i < NE) atomicAdd(&cnt[dst[i]], 1);
}
__global__ void csr_scan(const int* __restrict__ cnt, int* __restrict__ rowptr,
                         int* __restrict__ cursor, float* __restrict__ inv) {
    __shared__ int ps[1024];
    int t = threadIdx.x;
    const int CH = (NN + 1023) / 1024;
    int base = t * CH;
    int s = 0;
#pragma unroll
    for (int i = 0; i < CH; i++) { int id = base + i; if (id < NN) s += cnt[id]; }
    ps[t] = s;
    __syncthreads();
    for (int d = 1; d < 1024; d <<= 1) {
        int v = (t >= d) ? ps[t - d] : 0;
        __syncthreads();
        ps[t] += v;
        __syncthreads();
    }
    int off = (t == 0) ? 0 : ps[t - 1];
    for (int i = 0; i < CH; i++) {
        int id = base + i;
        if (id < NN) {
            rowptr[id] = off;
            cursor[id] = off;
            int c = cnt[id];
            inv[id] = 1.f / (float)max(c, 1);
            off += c;
        }
    }
    if (t == 1023) rowptr[NN] = NE;
}
__global__ void csr_scatter(const int* __restrict__ dst, int* __restrict__ cursor,
                            int* __restrict__ elist) {
    int i = blockIdx.x * blockDim.x + threadIdx.x;
    if (i < NE) {
        int p = atomicAdd(&cursor[dst[i]], 1);
        elist[p] = i;
    }
}

// ---------------- aggregation: CSR gather (no atomics) ----------------
__global__ void agg_gather_bf(const uint32_t* __restrict__ eh, const uint32_t* __restrict__ el,
                              const int* __restrict__ rowptr, const int* __restrict__ elist,
                              float* __restrict__ agg) {
    int warp = (blockIdx.x * blockDim.x + threadIdx.x) >> 5;
    int lane = threadIdx.x & 31;
    if (warp >= NN) return;
    int beg = rowptr[warp], end = rowptr[warp + 1];
    float a0 = 0.f, a1 = 0.f;
    for (int j = beg; j < end; j++) {
        int eid = elist[j];
        uint32_t h = eh[eid * 32 + lane];
        uint32_t l = el[eid * 32 + lane];
        __nv_bfloat162 hh = *reinterpret_cast<__nv_bfloat162*>(&h);
        __nv_bfloat162 ll = *reinterpret_cast<__nv_bfloat162*>(&l);
        a0 += __low2float(hh) + __low2float(ll);
        a1 += __high2float(hh) + __high2float(ll);
    }
    reinterpret_cast<float2*>(agg)[warp * 32 + lane] = make_float2(a0, a1);
}
__global__ void agg_gather_f32(const float2* __restrict__ e, const int* __restrict__ rowptr,
                               const int* __restrict__ elist, float* __restrict__ agg) {
    int warp = (blockIdx.x * blockDim.x + threadIdx.x) >> 5;
    int lane = threadIdx.x & 31;
    if (warp >= NN) return;
    int beg = rowptr[warp], end = rowptr[warp + 1];
    float a0 = 0.f, a1 = 0.f;
    for (int j = beg; j < end; j++) {
        float2 v = e[elist[j] * 32 + lane];
        a0 += v.x; a1 += v.y;
    }
    reinterpret_cast<float2*>(agg)[warp * 32 + lane] = make_float2(a0, a1);
}

// ---------------- batch counts ----------------
__global__ void count_idx(const int* __restrict__ idx, float* __restrict__ cnt, int n) {
    int i = blockIdx.x * blockDim.x + threadIdx.x;
    if (i < n) atomicAdd(&cnt[idx[i]], 1.f);
}
__global__ void make_inv(const float* __restrict__ cnt, float* __restrict__ inv, int n) {
    int i = blockIdx.x * blockDim.x + threadIdx.x;
    if (i < n) inv[i] = 1.f / fmaxf(cnt[i], 1.f);
}

// ---------------- PU = u @ We4 + be  (64 graphs x 64 cols) ----------------
template <int UW>
__global__ void pu_kernel(const float* __restrict__ u, const float* __restrict__ W4,
                          const float* __restrict__ be, float* __restrict__ PU) {
    int c = threadIdx.x;
    int b = blockIdx.x * blockDim.y + threadIdx.y;
    float acc = be[c];
#pragma unroll 8
    for (int k = 0; k < UW; k++) acc = fmaf(u[b * 64 + k], W4[k * 64 + c], acc);
    PU[b * 64 + c] = acc;
}

// ---------------- P = x @ [We1|We2]  (M=128/block, N=128, K=64, bf16-split) ----------------
__global__ void __launch_bounds__(256)
p_gemm(const __nv_bfloat16* __restrict__ xh, const __nv_bfloat16* __restrict__ xl,
       const uint32_t* __restrict__ bfrag, float* __restrict__ P) {
    constexpr int LDA = 64 * 2 + 16;     // 144
    constexpr int ASZ = 128 * LDA;
    constexpr int SM_B = 2 * ASZ;
    constexpr int BF_U32 = 4 * 16 * 32 * 4;

    extern __shared__ char smem[];
    const uint32_t sb = smem_u32(smem);
    const int tid = threadIdx.x;
    const int wid = tid >> 5;
    const int lane = tid & 31;
    const int nbase = blockIdx.x * 128;

    // stage A (contiguous node rows), RU = 8 uint4/row
    for (int it = tid; it < 128 * 8; it += 256) {
        int r = it >> 3, j = it & 7;
        int nn = min(nbase + r, NN - 1);
        uint4 vh = ((const uint4*)xh)[nn * 8 + j];
        uint4 vl = ((const uint4*)xl)[nn * 8 + j];
        uint32_t da = sb + r * LDA + j * 16;
        asm volatile("st.shared.v4.b32 [%0], {%1, %2, %3, %4};" :: "r"(da),
                     "r"(vh.x), "r"(vh.y), "r"(vh.z), "r"(vh.w) : "memory");
        asm volatile("st.shared.v4.b32 [%0], {%1, %2, %3, %4};" :: "r"(da + ASZ),
                     "r"(vl.x), "r"(vl.y), "r"(vl.z), "r"(vl.w) : "memory");
    }
    {
        const uint4* s4 = (const uint4*)bfrag;
        uint4* d4 = (uint4*)(smem + SM_B);
        for (int i = tid; i < BF_U32 / 4; i += 256) d4[i] = s4[i];
    }
    __syncthreads();

    float acc[16][4];
#pragma unroll
    for (int nt = 0; nt < 16; nt++)
#pragma unroll
        for (int r = 0; r < 4; r++) acc[nt][r] = 0.f;

    const uint32_t arow = sb + (wid * 16 + (lane & 15)) * LDA + (lane >> 4) * 16;
#pragma unroll
    for (int kt = 0; kt < 4; kt++) {
        uint32_t Ah[4], Al[4];
        ldmx4(Ah, arow + kt * 32);
        ldmx4(Al, arow + kt * 32 + ASZ);
        const uint32_t baddr = sb + SM_B + (uint32_t)(kt * 16 * 32 + lane) * 16;
#pragma unroll
        for (int nt = 0; nt < 16; nt++) {
            uint32_t bb[4];
            lds128(bb, baddr + nt * 512);
            mma16816(acc[nt], Ah, bb);
            mma16816(acc[nt], Al, bb);
            mma16816(acc[nt], Ah, bb + 2);
        }
    }

    const int r0 = wid * 16 + (lane >> 2);
    const int cb = 2 * (lane & 3);
#pragma unroll
    for (int half = 0; half < 2; half++) {
        int row = r0 + 8 * half;
        int nn = nbase + row;
        if (nn < NN) {
            float* po = P + (size_t)nn * 128 + cb;
#pragma unroll
            for (int nt = 0; nt < 16; nt++)
                asm volatile("st.global.v2.f32 [%0], {%1,%2};"
                             :: "l"(po + nt * 8), "f"(acc[nt][2 * half]),
                                "f"(acc[nt][2 * half + 1]) : "memory");
        }
    }
}

// ---------------- edge GEMM: e' = relu(e@We3 + P1[src] + P2[dst] + PU[b]) ----------------
template <int EW, bool FINAL>
__global__ void __launch_bounds__(256)
edge_gemm(const __nv_bfloat16* __restrict__ ehi, const __nv_bfloat16* __restrict__ eli,
          const int* __restrict__ src, const int* __restrict__ dst,
          const int* __restrict__ batch,
          const uint32_t* __restrict__ bfrag, const float* __restrict__ P,
          const float* __restrict__ PU,
          float* __restrict__ e_out, __nv_bfloat16* __restrict__ eho,
          __nv_bfloat16* __restrict__ elo) {
    constexpr int RU = EW / 8;
    constexpr int NKT = EW / 16;
    constexpr int LDA = EW * 2 + 16;
    constexpr int ASZ = 128 * LDA;
    constexpr int SM_A = 1536;
    constexpr int SM_B = SM_A + 2 * ASZ;
    constexpr int BF_U32 = NKT * 8 * 32 * 4;

    extern __shared__ char smem[];
    int* sT = (int*)(smem);
    int* dT = (int*)(smem + 512);
    int* bT = (int*)(smem + 1024);
    const uint32_t sb = smem_u32(smem);

    const int tid = threadIdx.x;
    const int wid = tid >> 5;
    const int lane = tid & 31;
    const int ebase = blockIdx.x * 128;

    if (tid < 128) {
        int ee = min(ebase + tid, NE - 1);
        int s = src[ee];
        sT[tid] = s; dT[tid] = dst[ee]; bT[tid] = batch[s];
    }

    // stage A: contiguous e rows (hi at SM_A, lo at SM_A+ASZ)
    for (int it = tid; it < 128 * RU; it += 256) {
        int r = it / RU, j = it - r * RU;
        int ee = min(ebase + r, NE - 1);
        uint4 vh = ((const uint4*)ehi)[ee * RU + j];
        uint4 vl = ((const uint4*)eli)[ee * RU + j];
        uint32_t da = sb + SM_A + r * LDA + j * 16;
        asm volatile("st.shared.v4.b32 [%0], {%1, %2, %3, %4};" :: "r"(da),
                     "r"(vh.x), "r"(vh.y), "r"(vh.z), "r"(vh.w) : "memory");
        asm volatile("st.shared.v4.b32 [%0], {%1, %2, %3, %4};" :: "r"(da + ASZ),
                     "r"(vl.x), "r"(vl.y), "r"(vl.z), "r"(vl.w) : "memory");
    }
    {
        const uint4* s4 = (const uint4*)bfrag;
        uint4* d4 = (uint4*)(smem + SM_B);
        for (int i = tid; i < BF_U32 / 4; i += 256) d4[i] = s4[i];
    }
    __syncthreads();

    float acc[8][4];
#pragma unroll
    for (int nt = 0; nt < 8; nt++)
#pragma unroll
        for (int r = 0; r < 4; r++) acc[nt][r] = 0.f;

    const uint32_t arow = sb + SM_A + (wid * 16 + (lane & 15)) * LDA + (lane >> 4) * 16;
#pragma unroll
    for (int kt = 0; kt < NKT; kt++) {
        uint32_t Ah[4], Al[4];
        ldmx4(Ah, arow + kt * 32);
        ldmx4(Al, arow + kt * 32 + ASZ);
        const uint32_t baddr = sb + SM_B + (uint32_t)(kt * 8 * 32 + lane) * 16;
#pragma unroll
        for (int nt = 0; nt < 8; nt++) {
            uint32_t bb[4];
            lds128(bb, baddr + nt * 512);
            mma16816(acc[nt], Ah, bb);
            mma16816(acc[nt], Al, bb);
            mma16816(acc[nt], Ah, bb + 2);
        }
    }

    // epilogue: add P1[src], P2[dst], PU[batch]; relu; write
    const int r0 = wid * 16 + (lane >> 2);
    const int cb = 2 * (lane & 3);
#pragma unroll
    for (int half = 0; half < 2; half++) {
        int row = r0 + 8 * half;
        int ee = ebase + row;
        if (ee < NE) {
            const float2* p1 = (const float2*)(P + (size_t)sT[row] * 128);
            const float2* p2 = (const float2*)(P + (size_t)dT[row] * 128 + 64);
            const float2* pu = (const float2*)(PU + bT[row] * 64);
            if (FINAL) {
                float* eo = e_out + (size_t)ee * 64 + cb;
#pragma unroll
                for (int nt = 0; nt < 8; nt++) {
                    int c2 = (nt * 8 + cb) >> 1;
                    float2 a = p1[c2], b = p2[c2], c = pu[c2];
                    float v0 = fmaxf(acc[nt][2 * half] + a.x + b.x + c.x, 0.f);
                    float v1 = fmaxf(acc[nt][2 * half + 1] + a.y + b.y + c.y, 0.f);
                    asm volatile("st.global.v2.f32 [%0], {%1,%2};"
                                 :: "l"(eo + nt * 8), "f"(v0), "f"(v1) : "memory");
                }
            } else {
                uint32_t* ho = (uint32_t*)eho + (size_t)ee * 32 + (lane & 3);
                uint32_t* lo = (uint32_t*)elo + (size_t)ee * 32 + (lane & 3);
#pragma unroll
                for (int nt = 0; nt < 8; nt++) {
                    int c2 = (nt * 8 + cb) >> 1;
                    float2 a = p1[c2], b = p2[c2], c = pu[c2];
                    float v0 = fmaxf(acc[nt][2 * half] + a.x + b.x + c.x, 0.f);
                    float v1 = fmaxf(acc[nt][2 * half + 1] + a.y + b.y + c.y, 0.f);
                    float h0 = __bfloat162float(__float2bfloat16(v0));
                    float h1 = __bfloat162float(__float2bfloat16(v1));
                    ho[nt * 4] = packbf(v0, v1);
                    lo[nt * 4] = packbf(v0 - h0, v1 - h1);
                }
            }
        }
    }
}

// ---------------- node MLP (warp-shuffle fp32) + fused pool + fused split ----------------
template <int DIN, int UW, bool FINAL>
__global__ void node_mlp(const float* __restrict__ x_in, const float* __restrict__ agg,
                         const float* __restrict__ inv_dst, const float* __restrict__ u,
                         const int* __restrict__ batch, const float* __restrict__ W,
                         const float* __restrict__ bias, float* __restrict__ x_out,
                         float* __restrict__ pool,
                         __nv_bfloat16* __restrict__ xh, __nv_bfloat16* __restrict__ xl) {
    extern __shared__ float Wsh[];
    for (int i = threadIdx.x; i < DIN * 64; i += blockDim.x) Wsh[i] = W[i];
    __syncthreads();
    const int lane = threadIdx.x & 31;
    const int warp = threadIdx.x >> 5;
    const int nwarp = blockDim.x >> 5;
    const float b0 = bias[lane], b1 = bias[lane + 32];
    constexpr int EPW = 4;
    constexpr int NCH = DIN / 32;

    for (int nbase = (blockIdx.x * nwarp + warp) * EPW; nbase < NN;
         nbase += gridDim.x * nwarp * EPW) {
        int ns[EPW], bN[EPW];
        float rc[EPW], acc0[EPW], acc1[EPW];
#pragma unroll
        for (int i = 0; i < EPW; i++) {
            int nn = min(nbase + i, NN - 1);
            ns[i] = nn; bN[i] = batch[nn]; rc[i] = inv_dst[nn];
            acc0[i] = b0; acc1[i] = b1;
        }
#pragma unroll
        for (int c = 0; c < NCH; c++) {
            float v[EPW];
#pragma unroll
            for (int i = 0; i < EPW; i++) {
                if (c < 2)       v[i] = x_in[ns[i] * 64 + c * 32 + lane];
                else if (c < 4)  v[i] = agg[ns[i] * 64 + (c - 2) * 32 + lane] * rc[i];
                else             v[i] = u[bN[i] * 64 + (c - 4) * 32 + lane];
            }
#pragma unroll
            for (int t = 0; t < 32; t++) {
                float w0 = Wsh[(c * 32 + t) * 64 + lane];
                float w1 = Wsh[(c * 32 + t) * 64 + 32 + lane];
#pragma unroll
                for (int i = 0; i < EPW; i++) {
                    float s = __shfl_sync(0xffffffffu, v[i], t);
                    acc0[i] = fmaf(s, w0, acc0[i]);
                    acc1[i] = fmaf(s, w1, acc1[i]);
                }
            }
        }
#pragma unroll
        for (int i = 0; i < EPW; i++) {
            if (nbase + i < NN) {
                float v0 = fmaxf(acc0[i], 0.f), v1 = fmaxf(acc1[i], 0.f);
                x_out[ns[i] * 64 + lane] = v0;
                x_out[ns[i] * 64 + 32 + lane] = v1;
                atomicAdd(&pool[bN[i] * 64 + lane], v0);
                atomicAdd(&pool[bN[i] * 64 + 32 + lane], v1);
                if (!FINAL) {
                    __nv_bfloat16 h0 = __float2bfloat16(v0);
                    __nv_bfloat16 h1 = __float2bfloat16(v1);
                    xh[ns[i] * 64 + lane] = h0;
                    xh[ns[i] * 64 + 32 + lane] = h1;
                    xl[ns[i] * 64 + lane] = __float2bfloat16(v0 - __bfloat162float(h0));
                    xl[ns[i] * 64 + 32 + lane] = __float2bfloat16(v1 - __bfloat162float(h1));
                }
            }
        }
    }
}

// ---------------- global MLP ----------------
template <int UW>
__global__ void glob_mlp(const float* __restrict__ xpool, const float* __restrict__ invb,
                         const float* __restrict__ u_in, const float* __restrict__ W,
                         const float* __restrict__ bias, float* __restrict__ u_out) {
    __shared__ float us[64];
    __shared__ float ps[64];
    int b = blockIdx.x;
    int h = threadIdx.x;
    if (h < UW) us[h] = u_in[b * 64 + h];
    ps[h] = xpool[b * 64 + h] * invb[b];
    __syncthreads();
    float acc = bias[h];
#pragma unroll 8
    for (int d = 0; d < 64; d++) acc = fmaf(ps[d], W[d * 64 + h], acc);
#pragma unroll 8
    for (int d = 0; d < UW; d++) acc = fmaf(us[d], W[(64 + d) * 64 + h], acc);
    u_out[b * 64 + h] = fmaxf(acc, 0.f);
}

// ---------------- host orchestration ----------------
extern "C" void kernel_launch(void* const* d_in, const int* in_sizes, int n_in,
                              void* d_out, int out_size) {
    const float* x     = (const float*)d_in[0];
    const int*   eidx  = (const int*)d_in[1];
    const float* e     = (const float*)d_in[2];
    const float* u     = (const float*)d_in[3];
    const int*   batch = (const int*)d_in[4];
    const float* gn = (const float*)d_in[5],  *bnb = (const float*)d_in[6];
    const float* ge = (const float*)d_in[7],  *beb = (const float*)d_in[8];
    const float* gg = (const float*)d_in[9],  *bgb = (const float*)d_in[10];
    const float* We[3] = {(const float*)d_in[11], (const float*)d_in[17], (const float*)d_in[23]};
    const float* be[3] = {(const float*)d_in[12], (const float*)d_in[18], (const float*)d_in[24]};
    const float* Wn[3] = {(const float*)d_in[13], (const float*)d_in[19], (const float*)d_in[25]};
    const float* bn[3] = {(const float*)d_in[14], (const float*)d_in[20], (const float*)d_in[26]};
    const float* Wg[3] = {(const float*)d_in[15], (const float*)d_in[21], (const float*)d_in[27]};
    const float* bg[3] = {(const float*)d_in[16], (const float*)d_in[22], (const float*)d_in[28]};

    const int* src = eidx;
    const int* dst = eidx + NE;

    float* out_x = (float*)d_out;
    float* out_e = out_x + (size_t)NN * 64;
    float* out_u = out_e + (size_t)NE * 64;

    float *p_x, *p_u, *p_P, *p_PU, *p_agg, *p_pool, *p_cbv, *p_id, *p_ib, *p_sums, *p_sc, *p_sf;
    __nv_bfloat16 *p_xh, *p_xl, *p_ehA, *p_elA, *p_ehB, *p_elB;
    uint32_t *p_bfe, *p_bfp;
    int *p_hist, *p_rowptr, *p_cursor, *p_elist;
    cudaGetSymbolAddress((void**)&p_x, g_x);
    cudaGetSymbolAddress((void**)&p_u, g_u);
    cudaGetSymbolAddress((void**)&p_P, g_P);
    cudaGetSymbolAddress((void**)&p_PU, g_PU);
    cudaGetSymbolAddress((void**)&p_agg, g_agg);
    cudaGetSymbolAddress((void**)&p_pool, g_pool);
    cudaGetSymbolAddress((void**)&p_cbv, g_cb);
    cudaGetSymbolAddress((void**)&p_id, g_id);
    cudaGetSymbolAddress((void**)&p_ib, g_ib);
    cudaGetSymbolAddress((void**)&p_sums, g_sums);
    cudaGetSymbolAddress((void**)&p_sc, g_sc);
    cudaGetSymbolAddress((void**)&p_sf, g_sf);
    cudaGetSymbolAddress((void**)&p_xh, g_xh);
    cudaGetSymbolAddress((void**)&p_xl, g_xl);
    cudaGetSymbolAddress((void**)&p_ehA, g_ehA);
    cudaGetSymbolAddress((void**)&p_elA, g_elA);
    cudaGetSymbolAddress((void**)&p_ehB, g_ehB);
    cudaGetSymbolAddress((void**)&p_elB, g_elB);
    cudaGetSymbolAddress((void**)&p_bfe, g_bfe);
    cudaGetSymbolAddress((void**)&p_bfp, g_bfp);
    cudaGetSymbolAddress((void**)&p_hist, g_hist);
    cudaGetSymbolAddress((void**)&p_rowptr, g_rowptr);
    cudaGetSymbolAddress((void**)&p_cursor, g_cursor);
    cudaGetSymbolAddress((void**)&p_elist, g_elist);

    const int SME32 = 1536 + 2 * (128 * (32 * 2 + 16)) + (32 / 16) * 8 * 32 * 16;   // 30208
    const int SME64 = 1536 + 2 * (128 * (64 * 2 + 16)) + (64 / 16) * 8 * 32 * 16;   // 54784
    const int SMP   = 2 * (128 * 144) + 4 * 16 * 32 * 16;                           // 69632
    cudaFuncSetAttribute(edge_gemm<32, false>, cudaFuncAttributeMaxDynamicSharedMemorySize, SME32);
    cudaFuncSetAttribute(edge_gemm<64, false>, cudaFuncAttributeMaxDynamicSharedMemorySize, SME64);
    cudaFuncSetAttribute(edge_gemm<64, true>,  cudaFuncAttributeMaxDynamicSharedMemorySize, SME64);
    cudaFuncSetAttribute(p_gemm, cudaFuncAttributeMaxDynamicSharedMemorySize, SMP);
    cudaFuncSetAttribute(node_mlp<160, 32, false>, cudaFuncAttributeMaxDynamicSharedMemorySize, 160 * 64 * 4);
    cudaFuncSetAttribute(node_mlp<192, 64, false>, cudaFuncAttributeMaxDynamicSharedMemorySize, 192 * 64 * 4);
    cudaFuncSetAttribute(node_mlp<192, 64, true>,  cudaFuncAttributeMaxDynamicSharedMemorySize, 192 * 64 * 4);

    // ---- CSR build ----
    cudaMemsetAsync(p_hist, 0, NN * sizeof(int));
    hist_dst<<<(NE + 255) / 256, 256>>>(dst, p_hist);
    csr_scan<<<1, 1024>>>(p_hist, p_rowptr, p_cursor, p_id);
    csr_scatter<<<(NE + 255) / 256, 256>>>(dst, p_cursor, p_elist);

    // ---- input BatchNorms + splits ----
    cudaMemsetAsync(p_sums, 0, 128 * sizeof(float));
    bn_stats4<64><<<296, 256>>>((const float4*)x, NN * 16, p_sums);
    bn_finalize<<<1, 64>>>(p_sums, gn, bnb, 1.f / NN, 64, p_sc, p_sf);
    bn_split_x<<<(NN * 64 + 255) / 256, 256>>>(x, p_sc, p_sf, p_x, p_xh, p_xl);

    cudaMemsetAsync(p_sums, 0, 128 * sizeof(float));
    bn_stats4<32><<<592, 256>>>((const float4*)e, NE * 8, p_sums);
    bn_finalize<<<1, 64>>>(p_sums, ge, beb, 1.f / NE, 32, p_sc, p_sf);
    bn_split_e<<<(NE * 32 + 255) / 256, 256>>>(e, p_sc, p_sf, p_ehA, p_elA);

    cudaMemsetAsync(p_sums, 0, 128 * sizeof(float));
    bn_stats4<32><<<2, 256>>>((const float4*)u, NB * 8, p_sums);
    bn_finalize<<<1, 64>>>(p_sums, gg, bgb, 1.f / NB, 32, p_sc, p_sf);
    bn_apply_u<<<(NB * 32 + 63) / 64, 64>>>(u, p_sc, p_sf, p_u);

    // ---- batch counts ----
    cudaMemsetAsync(p_cbv, 0, NB * sizeof(float));
    count_idx<<<(NN + 255) / 256, 256>>>(batch, p_cbv, NN);
    make_inv<<<1, 64>>>(p_cbv, p_ib, NB);

    // ---- weight fragment packs ----
    bfrag_pack_p<<<8, 256>>>(We[0], p_bfp + 0 * 8192);
    bfrag_pack_p<<<8, 256>>>(We[1], p_bfp + 1 * 8192);
    bfrag_pack_p<<<8, 256>>>(We[2], p_bfp + 2 * 8192);
    bfrag_pack<<<2, 256>>>(We[0] + 128 * 64, 32, p_bfe + 0 * 4096);
    bfrag_pack<<<4, 256>>>(We[1] + 128 * 64, 64, p_bfe + 1 * 4096);
    bfrag_pack<<<4, 256>>>(We[2] + 128 * 64, 64, p_bfe + 2 * 4096);

    const int EGRID = (NE + 127) / 128;
    const int PGRID = (NN + 127) / 128;
    const int NGRID = 938;
    const int AGRID = (NN * 32 + 255) / 256;

    // ---- layer 0 ----
    p_gemm<<<PGRID, 256, SMP>>>(p_xh, p_xl, p_bfp + 0 * 8192, p_P);
    pu_kernel<32><<<8, dim3(64, 8)>>>(p_u, We[0] + 160 * 64, be[0], p_PU);
    edge_gemm<32, false><<<EGRID, 256, SME32>>>(
        p_ehA, p_elA, src, dst, batch, p_bfe + 0 * 4096, p_P, p_PU, nullptr, p_ehB, p_elB);
    agg_gather_bf<<<AGRID, 256>>>((const uint32_t*)p_ehB, (const uint32_t*)p_elB,
                                  p_rowptr, p_elist, p_agg);
    cudaMemsetAsync(p_pool, 0, NB * 64 * sizeof(float));
    node_mlp<160, 32, false><<<NGRID, 256, 160 * 64 * 4>>>(
        p_x, p_agg, p_id, p_u, batch, Wn[0], bn[0], p_x, p_pool, p_xh, p_xl);
    glob_mlp<32><<<NB, 64>>>(p_pool, p_ib, p_u, Wg[0], bg[0], p_u);

    // ---- layer 1 ----
    p_gemm<<<PGRID, 256, SMP>>>(p_xh, p_xl, p_bfp + 1 * 8192, p_P);
    pu_kernel<64><<<8, dim3(64, 8)>>>(p_u, We[1] + 192 * 64, be[1], p_PU);
    edge_gemm<64, false><<<EGRID, 256, SME64>>>(
        p_ehB, p_elB, src, dst, batch, p_bfe + 1 * 4096, p_P, p_PU, nullptr, p_ehA, p_elA);
    agg_gather_bf<<<AGRID, 256>>>((const uint32_t*)p_ehA, (const uint32_t*)p_elA,
                                  p_rowptr, p_elist, p_agg);
    cudaMemsetAsync(p_pool, 0, NB * 64 * sizeof(float));
    node_mlp<192, 64, false><<<NGRID, 256, 192 * 64 * 4>>>(
        p_x, p_agg, p_id, p_u, batch, Wn[1], bn[1], p_x, p_pool, p_xh, p_xl);
    glob_mlp<64><<<NB, 64>>>(p_pool, p_ib, p_u, Wg[1], bg[1], p_u);

    // ---- layer 2 (final: write out_e / out_x / out_u) ----
    p_gemm<<<PGRID, 256, SMP>>>(p_xh, p_xl, p_bfp + 2 * 8192, p_P);
    pu_kernel<64><<<8, dim3(64, 8)>>>(p_u, We[2] + 192 * 64, be[2], p_PU);
    edge_gemm<64, true><<<EGRID, 256, SME64>>>(
        p_ehA, p_elA, src, dst, batch, p_bfe + 2 * 4096, p_P, p_PU, out_e, nullptr, nullptr);
    agg_gather_f32<<<AGRID, 256>>>((const float2*)out_e, p_rowptr, p_elist, p_agg);
    cudaMemsetAsync(p_pool, 0, NB * 64 * sizeof(float));
    node_mlp<192, 64, true><<<NGRID, 256, 192 * 64 * 4>>>(
        p_x, p_agg, p_id, p_u, batch, Wn[2], bn[2], out_x, p_pool, nullptr, nullptr);
    glob_mlp<64><<<NB, 64>>>(p_pool, p_ib, p_u, Wg[2], bg[2], out_u);
}